// round 12
// baseline (speedup 1.0000x reference)
#include <cuda_runtime.h>

#define BB 128   // batch
#define TT 128   // timesteps
#define NN 100   // subactors
#define HH 16    // hidden
#define SS 6     // state
#define GG 48    // 3*H gates
#define XS (NN * SS)   // x stride per t

typedef unsigned long long ull;

// scratch: h states, [n][t][k][b]  (105 MB) — b contiguous (proven-coalesced layout)
__device__ float g_h[(size_t)NN * TT * HH * BB];

// ---- packed f32x2 helpers ----
__device__ __forceinline__ ull ffma2(ull a, ull b, ull c) {
    ull d; asm("fma.rn.f32x2 %0, %1, %2, %3;" : "=l"(d) : "l"(a), "l"(b), "l"(c)); return d;
}
__device__ __forceinline__ ull pack2(float lo, float hi) {
    ull r; asm("mov.b64 %0, {%1, %2};" : "=l"(r) : "f"(lo), "f"(hi)); return r;
}
__device__ __forceinline__ float2 unpack2(ull v) {
    float2 f; asm("mov.b64 {%0, %1}, %2;" : "=f"(f.x), "=f"(f.y) : "l"(v)); return f;
}
__device__ __forceinline__ float hadd2(ull v) { float2 f = unpack2(v); return f.x + f.y; }
// ---- fast activations (MUFU-based, ~1e-6 rel err) ----
__device__ __forceinline__ float fex2(float x) { float y; asm("ex2.approx.f32 %0, %1;" : "=f"(y) : "f"(x)); return y; }
__device__ __forceinline__ float frcp(float x) { float y; asm("rcp.approx.f32 %0, %1;" : "=f"(y) : "f"(x)); return y; }
__device__ __forceinline__ float fsigmoid(float x) {
    return frcp(1.0f + fex2(-1.4426950408889634f * x));
}
__device__ __forceinline__ float ftanh_(float x) {
    return fmaf(-2.0f, frcp(1.0f + fex2(2.8853900817779268f * x)), 1.0f);
}

// ================= Kernel 1: GRU recurrence (weights in registers) =================
// Lane l (0..15) owns r-gate l, z-gate l, n-gate l as K-pair register weights.
// 4 sequences per 16-lane group; h exchanged via padded smem (broadcast loads).
__global__ void __launch_bounds__(64, 5)
actor_gru_kernel(const float* __restrict__ x,
                 const float* __restrict__ Wih, const float* __restrict__ Whh,
                 const float* __restrict__ bih, const float* __restrict__ bhh)
{
    __shared__ __align__(16) float hbuf[2][4][80];   // [parity][group][s*16+k] pad80
    __shared__ __align__(16) float xsm[2][4][40];    // [parity][group][s*8+2j]

    const int n    = blockIdx.x >> 3;
    const int qb   = blockIdx.x & 7;
    const int tid  = threadIdx.x;
    const int l    = tid & 15;
    const int g    = tid >> 4;          // 0..3
    const int w    = tid >> 5;          // warp 0..1
    const int lane = tid & 31;

    // ---------------- weights -> registers (one-time, K-pairs) ----------------
    const float* WhN = Whh + n * GG * HH;
    const float* WiN = Wih + n * GG * SS;
    ull Whr[8], Whz[8], Whn_[8];
    {
        const ulonglong2* pr = reinterpret_cast<const ulonglong2*>(WhN + l * HH);
        const ulonglong2* pz = reinterpret_cast<const ulonglong2*>(WhN + (16 + l) * HH);
        const ulonglong2* pn = reinterpret_cast<const ulonglong2*>(WhN + (32 + l) * HH);
#pragma unroll
        for (int k4 = 0; k4 < 4; k4++) {
            ulonglong2 vr = pr[k4]; Whr[2 * k4] = vr.x; Whr[2 * k4 + 1] = vr.y;
            ulonglong2 vz = pz[k4]; Whz[2 * k4] = vz.x; Whz[2 * k4 + 1] = vz.y;
            ulonglong2 vn = pn[k4]; Whn_[2 * k4] = vn.x; Whn_[2 * k4 + 1] = vn.y;
        }
    }
    ull Wxr[3], Wxz[3], Wxn[3];
#pragma unroll
    for (int j = 0; j < 3; j++) {
        Wxr[j] = *reinterpret_cast<const ull*>(WiN + l * SS + 2 * j);
        Wxz[j] = *reinterpret_cast<const ull*>(WiN + (16 + l) * SS + 2 * j);
        Wxn[j] = *reinterpret_cast<const ull*>(WiN + (32 + l) * SS + 2 * j);
    }
    const ull Rbr = pack2(bih[n * GG + l] + bhh[n * GG + l], 0.0f);
    const ull Rbz = pack2(bih[n * GG + 16 + l] + bhh[n * GG + 16 + l], 0.0f);
    const ull Rbx = pack2(bih[n * GG + 32 + l], 0.0f);
    const ull Rbh = pack2(bhh[n * GG + 32 + l], 0.0f);

    // zero this warp's groups of hbuf[0]
#pragma unroll
    for (int i = lane; i < 160; i += 32)
        hbuf[0][2 * w + (i >> 7)][i & 127] = 0.0f;
#pragma unroll
    for (int i = lane; i < 48; i += 32)
        hbuf[0][2 * w + 1][32 + i] = 0.0f;

    // x staging (lane < 24): this warp stages its 8 seqs
    const int sl = lane / 3, jx = lane % 3;
    const int bg = qb * 16 + w * 8 + sl;
    const int sgg = 2 * w + (sl >> 2), sss = sl & 3;
    const float* xsrc = x + (size_t)bg * TT * XS + n * SS + 2 * jx;
    if (lane < 24)
        *reinterpret_cast<ull*>(&xsm[0][sgg][sss * 8 + 2 * jx]) =
            *reinterpret_cast<const ull*>(xsrc);
    __syncwarp();

    // ---------------- recurrence ----------------
    const int b0 = qb * 16 + g * 4;
    float ownh[4] = { 0.0f, 0.0f, 0.0f, 0.0f };
    // [n][t][k][b]: store pairs (b0,b0+1) and (b0+2,b0+3) at row k=l
    float* ghp = g_h + (((size_t)n * TT) * HH + l) * BB + b0;

#pragma unroll 1
    for (int t = 0; t < TT; t++) {
        const int par = t & 1;

        if (lane < 24) {
            const float* ps = xsrc + (size_t)((t + 1 < TT) ? (t + 1) : t) * XS;
            *reinterpret_cast<ull*>(&xsm[par ^ 1][sgg][sss * 8 + 2 * jx]) =
                *reinterpret_cast<const ull*>(ps);
        }
        __syncwarp();

        ull ar[4], az[4], ah[4], ax[4];
#pragma unroll
        for (int s = 0; s < 4; s++) {
            ar[s] = Rbr; az[s] = Rbz; ah[s] = Rbh; ax[s] = Rbx;
        }

#pragma unroll
        for (int s = 0; s < 4; s++) {
            const ulonglong2* hp = reinterpret_cast<const ulonglong2*>(&hbuf[par][g][s * 16]);
            ulonglong2 va = hp[0], vb = hp[1], vc = hp[2], vd = hp[3];
            ar[s] = ffma2(va.x, Whr[0], ar[s]); az[s] = ffma2(va.x, Whz[0], az[s]); ah[s] = ffma2(va.x, Whn_[0], ah[s]);
            ar[s] = ffma2(va.y, Whr[1], ar[s]); az[s] = ffma2(va.y, Whz[1], az[s]); ah[s] = ffma2(va.y, Whn_[1], ah[s]);
            ar[s] = ffma2(vb.x, Whr[2], ar[s]); az[s] = ffma2(vb.x, Whz[2], az[s]); ah[s] = ffma2(vb.x, Whn_[2], ah[s]);
            ar[s] = ffma2(vb.y, Whr[3], ar[s]); az[s] = ffma2(vb.y, Whz[3], az[s]); ah[s] = ffma2(vb.y, Whn_[3], ah[s]);
            ar[s] = ffma2(vc.x, Whr[4], ar[s]); az[s] = ffma2(vc.x, Whz[4], az[s]); ah[s] = ffma2(vc.x, Whn_[4], ah[s]);
            ar[s] = ffma2(vc.y, Whr[5], ar[s]); az[s] = ffma2(vc.y, Whz[5], az[s]); ah[s] = ffma2(vc.y, Whn_[5], ah[s]);
            ar[s] = ffma2(vd.x, Whr[6], ar[s]); az[s] = ffma2(vd.x, Whz[6], az[s]); ah[s] = ffma2(vd.x, Whn_[6], ah[s]);
            ar[s] = ffma2(vd.y, Whr[7], ar[s]); az[s] = ffma2(vd.y, Whz[7], az[s]); ah[s] = ffma2(vd.y, Whn_[7], ah[s]);
            const ulonglong2* xp = reinterpret_cast<const ulonglong2*>(&xsm[par][g][s * 8]);
            ulonglong2 xv = xp[0];
            ull x2 = *reinterpret_cast<const ull*>(&xsm[par][g][s * 8 + 4]);
            ar[s] = ffma2(xv.x, Wxr[0], ar[s]); az[s] = ffma2(xv.x, Wxz[0], az[s]); ax[s] = ffma2(xv.x, Wxn[0], ax[s]);
            ar[s] = ffma2(xv.y, Wxr[1], ar[s]); az[s] = ffma2(xv.y, Wxz[1], az[s]); ax[s] = ffma2(xv.y, Wxn[1], ax[s]);
            ar[s] = ffma2(x2,   Wxr[2], ar[s]); az[s] = ffma2(x2,   Wxz[2], az[s]); ax[s] = ffma2(x2,   Wxn[2], ax[s]);
        }

#pragma unroll
        for (int s = 0; s < 4; s++) {
            float r  = fsigmoid(hadd2(ar[s]));
            float z  = fsigmoid(hadd2(az[s]));
            float np = fmaf(r, hadd2(ah[s]), hadd2(ax[s]));
            float nn_ = ftanh_(np);
            float hnew = fmaf(z, ownh[s] - nn_, nn_);
            ownh[s] = hnew;
            hbuf[par ^ 1][g][s * 16 + l] = hnew;
        }
        // scratch store: two 8B stores, b-contiguous (sector-friendly in [k][b] layout)
        *reinterpret_cast<ull*>(ghp)     = pack2(ownh[0], ownh[1]);
        *reinterpret_cast<ull*>(ghp + 2) = pack2(ownh[2], ownh[3]);
        ghp += (size_t)HH * BB;
    }
}

// ================= Kernel 2: MLP head (thread owns 2 sequences, zero redundancy) =================
__global__ void __launch_bounds__(128)
actor_mlp_kernel(const float* __restrict__ W1, const float* __restrict__ b1,
                 const float* __restrict__ W2, const float* __restrict__ b2,
                 const float* __restrict__ W3, const float* __restrict__ b3,
                 float* __restrict__ out)
{
    __shared__ __align__(16) ulonglong2 sw1[16][8];   // [j][k2] dup-packed
    __shared__ __align__(16) ulonglong2 sw2[16][8];
    __shared__ ull sb1[16], sb2[16], sw3[16];
    __shared__ float sb3s;

    const int n    = blockIdx.x;
    const int tq   = blockIdx.y;        // 0..31
    const int tid  = threadIdx.x;
    const int w    = tid >> 5;          // 0..3
    const int lane = tid & 31;
    const int t    = tq * 4 + w;

    {
        int j = tid >> 3, k2 = tid & 7;
        const float* p1 = W1 + n * HH * HH + j * HH + 2 * k2;
        sw1[j][k2] = make_ulonglong2(pack2(p1[0], p1[0]), pack2(p1[1], p1[1]));
        const float* p2 = W2 + n * HH * HH + j * HH + 2 * k2;
        sw2[j][k2] = make_ulonglong2(pack2(p2[0], p2[0]), pack2(p2[1], p2[1]));
    }
    if (tid < 16) {
        sb1[tid] = pack2(b1[n * HH + tid], b1[n * HH + tid]);
        sb2[tid] = pack2(b2[n * HH + tid], b2[n * HH + tid]);
        sw3[tid] = pack2(W3[n * HH + tid], W3[n * HH + tid]);
    }
    if (tid == 0) sb3s = b3[n];
    __syncthreads();
    const float Rb3 = sb3s;

    const float* hbase = g_h + ((size_t)n * TT + t) * HH * BB;

#pragma unroll 1
    for (int half = 0; half < 2; half++) {
        const int b0 = 2 * lane + 64 * half;

        // h: 16 × LDG.64, each warp-instruction spans 256B contiguous (proven pattern)
        ull h[16];
#pragma unroll
        for (int k = 0; k < 16; k++)
            h[k] = *reinterpret_cast<const ull*>(hbase + k * BB + b0);

        // layer 1
        ull y1[16];
#pragma unroll
        for (int j = 0; j < 16; j++) {
            ull acc = sb1[j];
#pragma unroll
            for (int k2 = 0; k2 < 8; k2++) {
                ulonglong2 wv = sw1[j][k2];
                acc = ffma2(h[2 * k2], wv.x, acc);
                acc = ffma2(h[2 * k2 + 1], wv.y, acc);
            }
            float2 v = unpack2(acc);
            y1[j] = pack2(fmaxf(v.x, 0.0f), fmaxf(v.y, 0.0f));
        }
        // layer 2 + 3
        ull acc3 = 0ULL;
#pragma unroll
        for (int j = 0; j < 16; j++) {
            ull acc = sb2[j];
#pragma unroll
            for (int k2 = 0; k2 < 8; k2++) {
                ulonglong2 wv = sw2[j][k2];
                acc = ffma2(y1[2 * k2], wv.x, acc);
                acc = ffma2(y1[2 * k2 + 1], wv.y, acc);
            }
            float2 v = unpack2(acc);
            acc3 = ffma2(pack2(fmaxf(v.x, 0.0f), fmaxf(v.y, 0.0f)), sw3[j], acc3);
        }
        float2 o = unpack2(acc3);

        float* ob = out + (size_t)n * BB * TT + (size_t)b0 * TT + t;
        ob[0]  = fmaxf(o.x + Rb3, 0.0f);
        ob[TT] = fmaxf(o.y + Rb3, 0.0f);
    }
}

extern "C" void kernel_launch(void* const* d_in, const int* in_sizes, int n_in,
                              void* d_out, int out_size)
{
    (void)in_sizes; (void)n_in; (void)out_size;
    const float* x   = (const float*)d_in[0];
    const float* Wih = (const float*)d_in[1];
    const float* Whh = (const float*)d_in[2];
    const float* bih = (const float*)d_in[3];
    const float* bhh = (const float*)d_in[4];
    const float* W1  = (const float*)d_in[5];
    const float* b1  = (const float*)d_in[6];
    const float* W2  = (const float*)d_in[7];
    const float* b2  = (const float*)d_in[8];
    const float* W3  = (const float*)d_in[9];
    const float* b3  = (const float*)d_in[10];
    float* out = (float*)d_out;

    actor_gru_kernel<<<NN * 8, 64>>>(x, Wih, Whh, bih, bhh);
    actor_mlp_kernel<<<dim3(NN, 32), 128>>>(W1, b1, W2, b2, W3, b3, out);
}

// round 16
// speedup vs baseline: 6.9011x; 6.9011x over previous
#include <cuda_runtime.h>

#define BB 128   // batch
#define TT 128   // timesteps
#define NN 100   // subactors
#define HH 16    // hidden
#define SS 6     // state
#define GG 48    // 3*H gates
#define XS (NN * SS)   // x stride per t

typedef unsigned long long ull;

// ---- packed f32x2 helpers ----
__device__ __forceinline__ ull ffma2(ull a, ull b, ull c) {
    ull d; asm("fma.rn.f32x2 %0, %1, %2, %3;" : "=l"(d) : "l"(a), "l"(b), "l"(c)); return d;
}
__device__ __forceinline__ ull pack2(float lo, float hi) {
    ull r; asm("mov.b64 %0, {%1, %2};" : "=l"(r) : "f"(lo), "f"(hi)); return r;
}
__device__ __forceinline__ float2 unpack2(ull v) {
    float2 f; asm("mov.b64 {%0, %1}, %2;" : "=f"(f.x), "=f"(f.y) : "l"(v)); return f;
}
__device__ __forceinline__ float hadd2(ull v) { float2 f = unpack2(v); return f.x + f.y; }
// ---- fast activations (MUFU-based, ~1e-6 rel err) ----
__device__ __forceinline__ float fex2(float x) { float y; asm("ex2.approx.f32 %0, %1;" : "=f"(y) : "f"(x)); return y; }
__device__ __forceinline__ float frcp(float x) { float y; asm("rcp.approx.f32 %0, %1;" : "=f"(y) : "f"(x)); return y; }
__device__ __forceinline__ float fsigmoid(float x) {
    return frcp(1.0f + fex2(-1.4426950408889634f * x));
}
__device__ __forceinline__ float ftanh_(float x) {
    return fmaf(-2.0f, frcp(1.0f + fex2(2.8853900817779268f * x)), 1.0f);
}

// ========== Fused GRU + MLP, no global scratch ==========
// Lane l (0..15) owns r/z/n gate l (K-pair register weights) and MLP1/2 output l.
// 4 sequences per 16-lane group. MLP runs one step behind the GRU, reusing the
// same hbuf reads for its layer-1 accumulation.
__global__ void __launch_bounds__(64, 5)
actor_fused_kernel(const float* __restrict__ x,
                   const float* __restrict__ Wih, const float* __restrict__ Whh,
                   const float* __restrict__ bih, const float* __restrict__ bhh,
                   const float* __restrict__ W1,  const float* __restrict__ b1,
                   const float* __restrict__ W2,  const float* __restrict__ b2,
                   const float* __restrict__ W3,  const float* __restrict__ b3,
                   float* __restrict__ out)
{
    __shared__ __align__(16) float hbuf[2][4][80];   // [parity][group][s*16+k] pad80
    __shared__ __align__(16) float xsm[2][4][40];    // [parity][group][s*8+2j]
    __shared__ __align__(16) float ybuf[4][80];      // y1 exchange [group][s*16+k]

    const int n    = blockIdx.x >> 3;
    const int qb   = blockIdx.x & 7;
    const int tid  = threadIdx.x;
    const int l    = tid & 15;
    const int g    = tid >> 4;          // 0..3
    const int w    = tid >> 5;          // warp 0..1
    const int lane = tid & 31;

    // ---------------- weights -> registers (one-time, K-pairs) ----------------
    const float* WhN = Whh + n * GG * HH;
    const float* WiN = Wih + n * GG * SS;
    ull Whr[8], Whz[8], Whn_[8];
    {
        const ulonglong2* pr = reinterpret_cast<const ulonglong2*>(WhN + l * HH);
        const ulonglong2* pz = reinterpret_cast<const ulonglong2*>(WhN + (16 + l) * HH);
        const ulonglong2* pn = reinterpret_cast<const ulonglong2*>(WhN + (32 + l) * HH);
#pragma unroll
        for (int k4 = 0; k4 < 4; k4++) {
            ulonglong2 vr = pr[k4]; Whr[2 * k4] = vr.x; Whr[2 * k4 + 1] = vr.y;
            ulonglong2 vz = pz[k4]; Whz[2 * k4] = vz.x; Whz[2 * k4 + 1] = vz.y;
            ulonglong2 vn = pn[k4]; Whn_[2 * k4] = vn.x; Whn_[2 * k4 + 1] = vn.y;
        }
    }
    ull Wxr[3], Wxz[3], Wxn[3];
#pragma unroll
    for (int j = 0; j < 3; j++) {
        Wxr[j] = *reinterpret_cast<const ull*>(WiN + l * SS + 2 * j);
        Wxz[j] = *reinterpret_cast<const ull*>(WiN + (16 + l) * SS + 2 * j);
        Wxn[j] = *reinterpret_cast<const ull*>(WiN + (32 + l) * SS + 2 * j);
    }
    const ull Rbr = pack2(bih[n * GG + l] + bhh[n * GG + l], 0.0f);
    const ull Rbz = pack2(bih[n * GG + 16 + l] + bhh[n * GG + 16 + l], 0.0f);
    const ull Rbx = pack2(bih[n * GG + 32 + l], 0.0f);
    const ull Rbh = pack2(bhh[n * GG + 32 + l], 0.0f);
    // MLP weights (K-pairs, lane owns output row l)
    ull W1k[8], W2k[8];
    {
        const ulonglong2* p1 = reinterpret_cast<const ulonglong2*>(W1 + n * HH * HH + l * HH);
        const ulonglong2* p2 = reinterpret_cast<const ulonglong2*>(W2 + n * HH * HH + l * HH);
#pragma unroll
        for (int k4 = 0; k4 < 4; k4++) {
            ulonglong2 v1 = p1[k4]; W1k[2 * k4] = v1.x; W1k[2 * k4 + 1] = v1.y;
            ulonglong2 v2 = p2[k4]; W2k[2 * k4] = v2.x; W2k[2 * k4 + 1] = v2.y;
        }
    }
    const float Rb1 = b1[n * HH + l];
    const float Rb2 = b2[n * HH + l];
    const float Rw3 = W3[n * HH + l];
    const float Rb3 = b3[n];

    // zero this warp's groups of hbuf[0]
#pragma unroll
    for (int i = lane; i < 160; i += 32)
        hbuf[0][2 * w + (i >> 7)][i & 127] = 0.0f;
#pragma unroll
    for (int i = lane; i < 48; i += 32)
        hbuf[0][2 * w + 1][32 + i] = 0.0f;

    // x staging (lane < 24): this warp stages its 8 seqs
    const int sl = lane / 3, jx = lane % 3;
    const int bg = qb * 16 + w * 8 + sl;
    const int sgg = 2 * w + (sl >> 2), sss = sl & 3;
    const float* xsrc = x + (size_t)bg * TT * XS + n * SS + 2 * jx;
    if (lane < 24)
        *reinterpret_cast<ull*>(&xsm[0][sgg][sss * 8 + 2 * jx]) =
            *reinterpret_cast<const ull*>(xsrc);
    __syncwarp();

    // ---------------- recurrence ----------------
    const int b0 = qb * 16 + g * 4;
    float ownh[4] = { 0.0f, 0.0f, 0.0f, 0.0f };
    float* op = out + (size_t)n * (BB * TT) + (size_t)(b0 + l) * TT;  // valid l<4
    float youts[4];

#pragma unroll 1
    for (int t = 0; t < TT; t++) {
        const int par = t & 1;

        if (lane < 24) {
            const float* ps = xsrc + (size_t)((t + 1 < TT) ? (t + 1) : t) * XS;
            *reinterpret_cast<ull*>(&xsm[par ^ 1][sgg][sss * 8 + 2 * jx]) =
                *reinterpret_cast<const ull*>(ps);
        }
        __syncwarp();   // orders prev-iter hbuf/ybuf traffic vs this iter

        ull ar[4], az[4], ah[4], ax[4], a1[4];
#pragma unroll
        for (int s = 0; s < 4; s++) {
            ar[s] = Rbr; az[s] = Rbz; ah[s] = Rbh; ax[s] = Rbx;
            a1[s] = pack2(Rb1, 0.0f);
        }

        // h_{t-1} reads feed BOTH the GRU gates (step t) and MLP layer1 (step t-1)
#pragma unroll
        for (int s = 0; s < 4; s++) {
            const ulonglong2* hp = reinterpret_cast<const ulonglong2*>(&hbuf[par][g][s * 16]);
            ulonglong2 va = hp[0], vb = hp[1], vc = hp[2], vd = hp[3];
            ar[s] = ffma2(va.x, Whr[0], ar[s]); az[s] = ffma2(va.x, Whz[0], az[s]); ah[s] = ffma2(va.x, Whn_[0], ah[s]); a1[s] = ffma2(va.x, W1k[0], a1[s]);
            ar[s] = ffma2(va.y, Whr[1], ar[s]); az[s] = ffma2(va.y, Whz[1], az[s]); ah[s] = ffma2(va.y, Whn_[1], ah[s]); a1[s] = ffma2(va.y, W1k[1], a1[s]);
            ar[s] = ffma2(vb.x, Whr[2], ar[s]); az[s] = ffma2(vb.x, Whz[2], az[s]); ah[s] = ffma2(vb.x, Whn_[2], ah[s]); a1[s] = ffma2(vb.x, W1k[2], a1[s]);
            ar[s] = ffma2(vb.y, Whr[3], ar[s]); az[s] = ffma2(vb.y, Whz[3], az[s]); ah[s] = ffma2(vb.y, Whn_[3], ah[s]); a1[s] = ffma2(vb.y, W1k[3], a1[s]);
            ar[s] = ffma2(vc.x, Whr[4], ar[s]); az[s] = ffma2(vc.x, Whz[4], az[s]); ah[s] = ffma2(vc.x, Whn_[4], ah[s]); a1[s] = ffma2(vc.x, W1k[4], a1[s]);
            ar[s] = ffma2(vc.y, Whr[5], ar[s]); az[s] = ffma2(vc.y, Whz[5], az[s]); ah[s] = ffma2(vc.y, Whn_[5], ah[s]); a1[s] = ffma2(vc.y, W1k[5], a1[s]);
            ar[s] = ffma2(vd.x, Whr[6], ar[s]); az[s] = ffma2(vd.x, Whz[6], az[s]); ah[s] = ffma2(vd.x, Whn_[6], ah[s]); a1[s] = ffma2(vd.x, W1k[6], a1[s]);
            ar[s] = ffma2(vd.y, Whr[7], ar[s]); az[s] = ffma2(vd.y, Whz[7], az[s]); ah[s] = ffma2(vd.y, Whn_[7], ah[s]); a1[s] = ffma2(vd.y, W1k[7], a1[s]);
            const ulonglong2* xp = reinterpret_cast<const ulonglong2*>(&xsm[par][g][s * 8]);
            ulonglong2 xv = xp[0];
            ull x2 = *reinterpret_cast<const ull*>(&xsm[par][g][s * 8 + 4]);
            ar[s] = ffma2(xv.x, Wxr[0], ar[s]); az[s] = ffma2(xv.x, Wxz[0], az[s]); ax[s] = ffma2(xv.x, Wxn[0], ax[s]);
            ar[s] = ffma2(xv.y, Wxr[1], ar[s]); az[s] = ffma2(xv.y, Wxz[1], az[s]); ax[s] = ffma2(xv.y, Wxn[1], ax[s]);
            ar[s] = ffma2(x2,   Wxr[2], ar[s]); az[s] = ffma2(x2,   Wxz[2], az[s]); ax[s] = ffma2(x2,   Wxn[2], ax[s]);
        }

        // GRU gates + state update (h_t), plus y1 of MLP(t-1)
#pragma unroll
        for (int s = 0; s < 4; s++) {
            float r  = fsigmoid(hadd2(ar[s]));
            float z  = fsigmoid(hadd2(az[s]));
            float np = fmaf(r, hadd2(ah[s]), hadd2(ax[s]));
            float nn_ = ftanh_(np);
            float hnew = fmaf(z, ownh[s] - nn_, nn_);
            ownh[s] = hnew;
            hbuf[par ^ 1][g][s * 16 + l] = hnew;
            ybuf[g][s * 16 + l] = fmaxf(hadd2(a1[s]), 0.0f);   // y1(t-1)
        }
        __syncwarp();   // y1 visible

        // MLP layer 2 + 3 for step t-1
        float sums[4];
#pragma unroll
        for (int s = 0; s < 4; s++) {
            const ulonglong2* yp = reinterpret_cast<const ulonglong2*>(&ybuf[g][s * 16]);
            ulonglong2 ya = yp[0], yb = yp[1], yc = yp[2], yd = yp[3];
            ull acc = pack2(Rb2, 0.0f);
            acc = ffma2(ya.x, W2k[0], acc); acc = ffma2(ya.y, W2k[1], acc);
            acc = ffma2(yb.x, W2k[2], acc); acc = ffma2(yb.y, W2k[3], acc);
            acc = ffma2(yc.x, W2k[4], acc); acc = ffma2(yc.y, W2k[5], acc);
            acc = ffma2(yd.x, W2k[6], acc); acc = ffma2(yd.y, W2k[7], acc);
            float y2 = fmaxf(hadd2(acc), 0.0f);
            float ps = y2 * Rw3;
            ps += __shfl_xor_sync(0xFFFFFFFFu, ps, 1, 16);
            ps += __shfl_xor_sync(0xFFFFFFFFu, ps, 2, 16);
            ps += __shfl_xor_sync(0xFFFFFFFFu, ps, 4, 16);
            ps += __shfl_xor_sync(0xFFFFFFFFu, ps, 8, 16);
            sums[s] = ps;
        }
        float mys = (l == 0) ? sums[0] : (l == 1) ? sums[1] : (l == 2) ? sums[2] : sums[3];
        const int tm = t - 1;                 // output timestep
        youts[tm & 3] = fmaxf(mys + Rb3, 0.0f);
        if (t > 0 && (tm & 3) == 3 && l < 4) {
            *reinterpret_cast<float4*>(op + tm - 3) =
                make_float4(youts[0], youts[1], youts[2], youts[3]);
        }
    }

    // -------- epilogue: MLP for t = 127 (h_127 is in hbuf[0], since last par=1) --------
    __syncwarp();
    {
        ull a1[4];
#pragma unroll
        for (int s = 0; s < 4; s++) a1[s] = pack2(Rb1, 0.0f);
#pragma unroll
        for (int s = 0; s < 4; s++) {
            const ulonglong2* hp = reinterpret_cast<const ulonglong2*>(&hbuf[0][g][s * 16]);
            ulonglong2 va = hp[0], vb = hp[1], vc = hp[2], vd = hp[3];
            a1[s] = ffma2(va.x, W1k[0], a1[s]); a1[s] = ffma2(va.y, W1k[1], a1[s]);
            a1[s] = ffma2(vb.x, W1k[2], a1[s]); a1[s] = ffma2(vb.y, W1k[3], a1[s]);
            a1[s] = ffma2(vc.x, W1k[4], a1[s]); a1[s] = ffma2(vc.y, W1k[5], a1[s]);
            a1[s] = ffma2(vd.x, W1k[6], a1[s]); a1[s] = ffma2(vd.y, W1k[7], a1[s]);
            ybuf[g][s * 16 + l] = fmaxf(hadd2(a1[s]), 0.0f);
        }
        __syncwarp();
        float sums[4];
#pragma unroll
        for (int s = 0; s < 4; s++) {
            const ulonglong2* yp = reinterpret_cast<const ulonglong2*>(&ybuf[g][s * 16]);
            ulonglong2 ya = yp[0], yb = yp[1], yc = yp[2], yd = yp[3];
            ull acc = pack2(Rb2, 0.0f);
            acc = ffma2(ya.x, W2k[0], acc); acc = ffma2(ya.y, W2k[1], acc);
            acc = ffma2(yb.x, W2k[2], acc); acc = ffma2(yb.y, W2k[3], acc);
            acc = ffma2(yc.x, W2k[4], acc); acc = ffma2(yc.y, W2k[5], acc);
            acc = ffma2(yd.x, W2k[6], acc); acc = ffma2(yd.y, W2k[7], acc);
            float y2 = fmaxf(hadd2(acc), 0.0f);
            float ps = y2 * Rw3;
            ps += __shfl_xor_sync(0xFFFFFFFFu, ps, 1, 16);
            ps += __shfl_xor_sync(0xFFFFFFFFu, ps, 2, 16);
            ps += __shfl_xor_sync(0xFFFFFFFFu, ps, 4, 16);
            ps += __shfl_xor_sync(0xFFFFFFFFu, ps, 8, 16);
            sums[s] = ps;
        }
        float mys = (l == 0) ? sums[0] : (l == 1) ? sums[1] : (l == 2) ? sums[2] : sums[3];
        youts[3] = fmaxf(mys + Rb3, 0.0f);
        if (l < 4) {
            *reinterpret_cast<float4*>(op + TT - 4) =
                make_float4(youts[0], youts[1], youts[2], youts[3]);
        }
    }
}

extern "C" void kernel_launch(void* const* d_in, const int* in_sizes, int n_in,
                              void* d_out, int out_size)
{
    (void)in_sizes; (void)n_in; (void)out_size;
    const float* x   = (const float*)d_in[0];
    const float* Wih = (const float*)d_in[1];
    const float* Whh = (const float*)d_in[2];
    const float* bih = (const float*)d_in[3];
    const float* bhh = (const float*)d_in[4];
    const float* W1  = (const float*)d_in[5];
    const float* b1  = (const float*)d_in[6];
    const float* W2  = (const float*)d_in[7];
    const float* b2  = (const float*)d_in[8];
    const float* W3  = (const float*)d_in[9];
    const float* b3  = (const float*)d_in[10];
    float* out = (float*)d_out;

    actor_fused_kernel<<<NN * 8, 64>>>(x, Wih, Whh, bih, bhh,
                                       W1, b1, W2, b2, W3, b3, out);
}

// round 17
// speedup vs baseline: 6.9022x; 1.0002x over previous
#include <cuda_runtime.h>

#define BB 128   // batch
#define TT 128   // timesteps
#define NN 100   // subactors
#define HH 16    // hidden
#define SS 6     // state
#define GG 48    // 3*H gates
#define XS (NN * SS)   // x stride per t

typedef unsigned long long ull;

// ---- packed f32x2 helpers ----
__device__ __forceinline__ ull ffma2(ull a, ull b, ull c) {
    ull d; asm("fma.rn.f32x2 %0, %1, %2, %3;" : "=l"(d) : "l"(a), "l"(b), "l"(c)); return d;
}
__device__ __forceinline__ ull pack2(float lo, float hi) {
    ull r; asm("mov.b64 %0, {%1, %2};" : "=l"(r) : "f"(lo), "f"(hi)); return r;
}
__device__ __forceinline__ float2 unpack2(ull v) {
    float2 f; asm("mov.b64 {%0, %1}, %2;" : "=f"(f.x), "=f"(f.y) : "l"(v)); return f;
}
__device__ __forceinline__ float hadd2(ull v) { float2 f = unpack2(v); return f.x + f.y; }
// ---- fast activations (MUFU-based, ~1e-6 rel err) ----
__device__ __forceinline__ float fex2(float x) { float y; asm("ex2.approx.f32 %0, %1;" : "=f"(y) : "f"(x)); return y; }
__device__ __forceinline__ float frcp(float x) { float y; asm("rcp.approx.f32 %0, %1;" : "=f"(y) : "f"(x)); return y; }
__device__ __forceinline__ float fsigmoid(float x) {
    return frcp(1.0f + fex2(-1.4426950408889634f * x));
}
__device__ __forceinline__ float ftanh_(float x) {
    return fmaf(-2.0f, frcp(1.0f + fex2(2.8853900817779268f * x)), 1.0f);
}

// ========== Fused GRU + MLP, no global scratch; 2 seqs per 16-lane group ==========
// Lane l (0..15) owns r/z/n gate l (K-pair register weights) and MLP1/2 output l.
// MLP runs one step behind the GRU, reusing the same hbuf reads for layer 1.
__global__ void __launch_bounds__(64, 6)
actor_fused_kernel(const float* __restrict__ x,
                   const float* __restrict__ Wih, const float* __restrict__ Whh,
                   const float* __restrict__ bih, const float* __restrict__ bhh,
                   const float* __restrict__ W1,  const float* __restrict__ b1,
                   const float* __restrict__ W2,  const float* __restrict__ b2,
                   const float* __restrict__ W3,  const float* __restrict__ b3,
                   float* __restrict__ out)
{
    __shared__ __align__(16) float hbuf[2][4][40];   // [parity][group][s*16+k] pad40
    __shared__ __align__(16) float xsm[2][4][20];    // [parity][group][s*8+2j] pad20
    __shared__ __align__(16) float ybuf[4][40];      // y1 exchange [group][s*16+k]

    const int n    = blockIdx.x >> 4;      // subactor
    const int qb   = blockIdx.x & 15;      // batch sixteenth (8 seqs)
    const int tid  = threadIdx.x;
    const int l    = tid & 15;
    const int g    = tid >> 4;             // group 0..3
    const int w    = tid >> 5;             // warp 0..1
    const int lane = tid & 31;

    // ---------------- weights -> registers (one-time, K-pairs) ----------------
    const float* WhN = Whh + n * GG * HH;
    const float* WiN = Wih + n * GG * SS;
    ull Whr[8], Whz[8], Whn_[8];
    {
        const ulonglong2* pr = reinterpret_cast<const ulonglong2*>(WhN + l * HH);
        const ulonglong2* pz = reinterpret_cast<const ulonglong2*>(WhN + (16 + l) * HH);
        const ulonglong2* pn = reinterpret_cast<const ulonglong2*>(WhN + (32 + l) * HH);
#pragma unroll
        for (int k4 = 0; k4 < 4; k4++) {
            ulonglong2 vr = pr[k4]; Whr[2 * k4] = vr.x; Whr[2 * k4 + 1] = vr.y;
            ulonglong2 vz = pz[k4]; Whz[2 * k4] = vz.x; Whz[2 * k4 + 1] = vz.y;
            ulonglong2 vn = pn[k4]; Whn_[2 * k4] = vn.x; Whn_[2 * k4 + 1] = vn.y;
        }
    }
    ull Wxr[3], Wxz[3], Wxn[3];
#pragma unroll
    for (int j = 0; j < 3; j++) {
        Wxr[j] = *reinterpret_cast<const ull*>(WiN + l * SS + 2 * j);
        Wxz[j] = *reinterpret_cast<const ull*>(WiN + (16 + l) * SS + 2 * j);
        Wxn[j] = *reinterpret_cast<const ull*>(WiN + (32 + l) * SS + 2 * j);
    }
    const ull Rbr = pack2(bih[n * GG + l] + bhh[n * GG + l], 0.0f);
    const ull Rbz = pack2(bih[n * GG + 16 + l] + bhh[n * GG + 16 + l], 0.0f);
    const ull Rbx = pack2(bih[n * GG + 32 + l], 0.0f);
    const ull Rbh = pack2(bhh[n * GG + 32 + l], 0.0f);
    ull W1k[8], W2k[8];
    {
        const ulonglong2* p1 = reinterpret_cast<const ulonglong2*>(W1 + n * HH * HH + l * HH);
        const ulonglong2* p2 = reinterpret_cast<const ulonglong2*>(W2 + n * HH * HH + l * HH);
#pragma unroll
        for (int k4 = 0; k4 < 4; k4++) {
            ulonglong2 v1 = p1[k4]; W1k[2 * k4] = v1.x; W1k[2 * k4 + 1] = v1.y;
            ulonglong2 v2 = p2[k4]; W2k[2 * k4] = v2.x; W2k[2 * k4 + 1] = v2.y;
        }
    }
    const float Rb1 = b1[n * HH + l];
    const float Rb2 = b2[n * HH + l];
    const float Rw3 = W3[n * HH + l];
    const float Rb3 = b3[n];

    // zero this warp's two groups of hbuf[0] (2 × 40 floats)
#pragma unroll
    for (int i = lane; i < 80; i += 32)
        hbuf[0][2 * w + (i >= 40)][i >= 40 ? i - 40 : i] = 0.0f;

    // x staging (lane < 12): this warp stages its 4 seqs (groups 2w, 2w+1)
    const int sl = lane / 3, jx = lane % 3;        // seq-local 0..3, pair index
    const int bg = qb * 8 + w * 4 + sl;            // global batch
    const int sgg = 2 * w + (sl >> 1), sss = sl & 1;
    const float* xsrc = x + (size_t)bg * TT * XS + n * SS + 2 * jx;
    if (lane < 12)
        *reinterpret_cast<ull*>(&xsm[0][sgg][sss * 8 + 2 * jx]) =
            *reinterpret_cast<const ull*>(xsrc);
    __syncwarp();

    // ---------------- recurrence ----------------
    const int b0 = qb * 8 + g * 2;
    float ownh[2] = { 0.0f, 0.0f };
    float* op = out + (size_t)n * (BB * TT) + (size_t)(b0 + l) * TT;  // valid l<2
    float youts[4];

#pragma unroll 1
    for (int t = 0; t < TT; t++) {
        const int par = t & 1;

        if (lane < 12) {
            const float* ps = xsrc + (size_t)((t + 1 < TT) ? (t + 1) : t) * XS;
            *reinterpret_cast<ull*>(&xsm[par ^ 1][sgg][sss * 8 + 2 * jx]) =
                *reinterpret_cast<const ull*>(ps);
        }
        __syncwarp();   // orders prev-iter hbuf/ybuf traffic vs this iter

        ull ar[2], az[2], ah[2], ax[2], a1[2];
#pragma unroll
        for (int s = 0; s < 2; s++) {
            ar[s] = Rbr; az[s] = Rbz; ah[s] = Rbh; ax[s] = Rbx;
            a1[s] = pack2(Rb1, 0.0f);
        }

        // h_{t-1} feeds BOTH the GRU gates (step t) and MLP layer1 (step t-1)
#pragma unroll
        for (int s = 0; s < 2; s++) {
            const ulonglong2* hp = reinterpret_cast<const ulonglong2*>(&hbuf[par][g][s * 16]);
            ulonglong2 va = hp[0], vb = hp[1], vc = hp[2], vd = hp[3];
            ar[s] = ffma2(va.x, Whr[0], ar[s]); az[s] = ffma2(va.x, Whz[0], az[s]); ah[s] = ffma2(va.x, Whn_[0], ah[s]); a1[s] = ffma2(va.x, W1k[0], a1[s]);
            ar[s] = ffma2(va.y, Whr[1], ar[s]); az[s] = ffma2(va.y, Whz[1], az[s]); ah[s] = ffma2(va.y, Whn_[1], ah[s]); a1[s] = ffma2(va.y, W1k[1], a1[s]);
            ar[s] = ffma2(vb.x, Whr[2], ar[s]); az[s] = ffma2(vb.x, Whz[2], az[s]); ah[s] = ffma2(vb.x, Whn_[2], ah[s]); a1[s] = ffma2(vb.x, W1k[2], a1[s]);
            ar[s] = ffma2(vb.y, Whr[3], ar[s]); az[s] = ffma2(vb.y, Whz[3], az[s]); ah[s] = ffma2(vb.y, Whn_[3], ah[s]); a1[s] = ffma2(vb.y, W1k[3], a1[s]);
            ar[s] = ffma2(vc.x, Whr[4], ar[s]); az[s] = ffma2(vc.x, Whz[4], az[s]); ah[s] = ffma2(vc.x, Whn_[4], ah[s]); a1[s] = ffma2(vc.x, W1k[4], a1[s]);
            ar[s] = ffma2(vc.y, Whr[5], ar[s]); az[s] = ffma2(vc.y, Whz[5], az[s]); ah[s] = ffma2(vc.y, Whn_[5], ah[s]); a1[s] = ffma2(vc.y, W1k[5], a1[s]);
            ar[s] = ffma2(vd.x, Whr[6], ar[s]); az[s] = ffma2(vd.x, Whz[6], az[s]); ah[s] = ffma2(vd.x, Whn_[6], ah[s]); a1[s] = ffma2(vd.x, W1k[6], a1[s]);
            ar[s] = ffma2(vd.y, Whr[7], ar[s]); az[s] = ffma2(vd.y, Whz[7], az[s]); ah[s] = ffma2(vd.y, Whn_[7], ah[s]); a1[s] = ffma2(vd.y, W1k[7], a1[s]);
            const ulonglong2* xp = reinterpret_cast<const ulonglong2*>(&xsm[par][g][s * 8]);
            ulonglong2 xv = xp[0];
            ull x2 = *reinterpret_cast<const ull*>(&xsm[par][g][s * 8 + 4]);
            ar[s] = ffma2(xv.x, Wxr[0], ar[s]); az[s] = ffma2(xv.x, Wxz[0], az[s]); ax[s] = ffma2(xv.x, Wxn[0], ax[s]);
            ar[s] = ffma2(xv.y, Wxr[1], ar[s]); az[s] = ffma2(xv.y, Wxz[1], az[s]); ax[s] = ffma2(xv.y, Wxn[1], ax[s]);
            ar[s] = ffma2(x2,   Wxr[2], ar[s]); az[s] = ffma2(x2,   Wxz[2], az[s]); ax[s] = ffma2(x2,   Wxn[2], ax[s]);
        }

        // GRU gates + state update (h_t), plus y1 of MLP(t-1)
#pragma unroll
        for (int s = 0; s < 2; s++) {
            float r  = fsigmoid(hadd2(ar[s]));
            float z  = fsigmoid(hadd2(az[s]));
            float np = fmaf(r, hadd2(ah[s]), hadd2(ax[s]));
            float nn_ = ftanh_(np);
            float hnew = fmaf(z, ownh[s] - nn_, nn_);
            ownh[s] = hnew;
            hbuf[par ^ 1][g][s * 16 + l] = hnew;
            ybuf[g][s * 16 + l] = fmaxf(hadd2(a1[s]), 0.0f);   // y1(t-1)
        }
        __syncwarp();   // y1 visible

        // MLP layer 2 + 3 for step t-1
        float sums[2];
#pragma unroll
        for (int s = 0; s < 2; s++) {
            const ulonglong2* yp = reinterpret_cast<const ulonglong2*>(&ybuf[g][s * 16]);
            ulonglong2 ya = yp[0], yb = yp[1], yc = yp[2], yd = yp[3];
            ull acc = pack2(Rb2, 0.0f);
            acc = ffma2(ya.x, W2k[0], acc); acc = ffma2(ya.y, W2k[1], acc);
            acc = ffma2(yb.x, W2k[2], acc); acc = ffma2(yb.y, W2k[3], acc);
            acc = ffma2(yc.x, W2k[4], acc); acc = ffma2(yc.y, W2k[5], acc);
            acc = ffma2(yd.x, W2k[6], acc); acc = ffma2(yd.y, W2k[7], acc);
            float y2 = fmaxf(hadd2(acc), 0.0f);
            float ps = y2 * Rw3;
            ps += __shfl_xor_sync(0xFFFFFFFFu, ps, 1, 16);
            ps += __shfl_xor_sync(0xFFFFFFFFu, ps, 2, 16);
            ps += __shfl_xor_sync(0xFFFFFFFFu, ps, 4, 16);
            ps += __shfl_xor_sync(0xFFFFFFFFu, ps, 8, 16);
            sums[s] = ps;
        }
        float mys = (l == 0) ? sums[0] : sums[1];
        const int tm = t - 1;
        youts[tm & 3] = fmaxf(mys + Rb3, 0.0f);
        if (t > 0 && (tm & 3) == 3 && l < 2) {
            *reinterpret_cast<float4*>(op + tm - 3) =
                make_float4(youts[0], youts[1], youts[2], youts[3]);
        }
    }

    // -------- epilogue: MLP for t = 127 (h_127 in hbuf[0]; last par was 1) --------
    __syncwarp();
    {
        ull a1[2];
#pragma unroll
        for (int s = 0; s < 2; s++) a1[s] = pack2(Rb1, 0.0f);
#pragma unroll
        for (int s = 0; s < 2; s++) {
            const ulonglong2* hp = reinterpret_cast<const ulonglong2*>(&hbuf[0][g][s * 16]);
            ulonglong2 va = hp[0], vb = hp[1], vc = hp[2], vd = hp[3];
            a1[s] = ffma2(va.x, W1k[0], a1[s]); a1[s] = ffma2(va.y, W1k[1], a1[s]);
            a1[s] = ffma2(vb.x, W1k[2], a1[s]); a1[s] = ffma2(vb.y, W1k[3], a1[s]);
            a1[s] = ffma2(vc.x, W1k[4], a1[s]); a1[s] = ffma2(vc.y, W1k[5], a1[s]);
            a1[s] = ffma2(vd.x, W1k[6], a1[s]); a1[s] = ffma2(vd.y, W1k[7], a1[s]);
            ybuf[g][s * 16 + l] = fmaxf(hadd2(a1[s]), 0.0f);
        }
        __syncwarp();
        float sums[2];
#pragma unroll
        for (int s = 0; s < 2; s++) {
            const ulonglong2* yp = reinterpret_cast<const ulonglong2*>(&ybuf[g][s * 16]);
            ulonglong2 ya = yp[0], yb = yp[1], yc = yp[2], yd = yp[3];
            ull acc = pack2(Rb2, 0.0f);
            acc = ffma2(ya.x, W2k[0], acc); acc = ffma2(ya.y, W2k[1], acc);
            acc = ffma2(yb.x, W2k[2], acc); acc = ffma2(yb.y, W2k[3], acc);
            acc = ffma2(yc.x, W2k[4], acc); acc = ffma2(yc.y, W2k[5], acc);
            acc = ffma2(yd.x, W2k[6], acc); acc = ffma2(yd.y, W2k[7], acc);
            float y2 = fmaxf(hadd2(acc), 0.0f);
            float ps = y2 * Rw3;
            ps += __shfl_xor_sync(0xFFFFFFFFu, ps, 1, 16);
            ps += __shfl_xor_sync(0xFFFFFFFFu, ps, 2, 16);
            ps += __shfl_xor_sync(0xFFFFFFFFu, ps, 4, 16);
            ps += __shfl_xor_sync(0xFFFFFFFFu, ps, 8, 16);
            sums[s] = ps;
        }
        float mys = (l == 0) ? sums[0] : sums[1];
        youts[3] = fmaxf(mys + Rb3, 0.0f);
        if (l < 2) {
            *reinterpret_cast<float4*>(op + TT - 4) =
                make_float4(youts[0], youts[1], youts[2], youts[3]);
        }
    }
}

extern "C" void kernel_launch(void* const* d_in, const int* in_sizes, int n_in,
                              void* d_out, int out_size)
{
    (void)in_sizes; (void)n_in; (void)out_size;
    const float* x   = (const float*)d_in[0];
    const float* Wih = (const float*)d_in[1];
    const float* Whh = (const float*)d_in[2];
    const float* bih = (const float*)d_in[3];
    const float* bhh = (const float*)d_in[4];
    const float* W1  = (const float*)d_in[5];
    const float* b1  = (const float*)d_in[6];
    const float* W2  = (const float*)d_in[7];
    const float* b2  = (const float*)d_in[8];
    const float* W3  = (const float*)d_in[9];
    const float* b3  = (const float*)d_in[10];
    float* out = (float*)d_out;

    actor_fused_kernel<<<NN * 16, 64>>>(x, Wih, Whh, bih, bhh,
                                        W1, b1, W2, b2, W3, b3, out);
}